// round 4
// baseline (speedup 1.0000x reference)
#include <cuda_runtime.h>

#define TDIM 512
#define NREC 256
#define NIN 10
#define NOUT 3
#define BATCH 1024
#define ROWS 8
#define NB (BATCH/ROWS)     // 128 blocks
#define NT 256              // 8 warps, 2 per SMSP
#define JS 128              // j rows cached in SMEM (per column)
#define WPAD 132            // padded W row (floats): conflict-free LDS.128
#define NSTREAM ((NREC-JS)/4)   // 32 packs of 4 j streamed from L2

typedef unsigned long long u64;

__device__ ulonglong2 g_Wst[NSTREAM * NREC];   // [ (j-128)/4 ][ c ] : 4-j weight packs, 128 KB
__device__ float g_l2p[NB];
__device__ unsigned int g_ctr;

static __device__ __forceinline__ u64 pk(float a, float b){
    u64 r; asm("mov.b64 %0,{%1,%2};":"=l"(r):"f"(a),"f"(b)); return r;
}
static __device__ __forceinline__ u64 fm2(u64 a, u64 b, u64 c){
    u64 d; asm("fma.rn.f32x2 %0,%1,%2,%3;":"=l"(d):"l"(a),"l"(b),"l"(c)); return d;
}
static __device__ __forceinline__ float2 up(u64 v){
    float2 f; asm("mov.b64 {%0,%1},%2;":"=f"(f.x),"=f"(f.y):"l"(v)); return f;
}

// g_Wst[k][c] = W_rec[c][128+4k .. 128+4k+3]
__global__ void prep_kernel(const float* __restrict__ W){
    int c = threadIdx.x;   // 256 threads
    const ulonglong2* row = (const ulonglong2*)(W + c * NREC);
    #pragma unroll
    for (int k = 0; k < NSTREAM; k++)
        g_Wst[k * NREC + c] = row[JS/4 + k];
}

__global__ __launch_bounds__(NT, 1)
void rnn_kernel(const float* __restrict__ x,
                const float* __restrict__ noise,
                const float* __restrict__ W_in,
                const float* __restrict__ W_rec,
                const float* __restrict__ W_out,
                const float* __restrict__ b_out,
                const float* __restrict__ bias,
                float* __restrict__ out, int out_size)
{
    extern __shared__ float sm[];
    float* Wsm = sm;                         // [256][WPAD] (j < 128 per col), 135 KB
    float* rT  = Wsm + NREC * WPAD;          // [2][ROWS][NREC] double-buffered
    float* WoS = rT + 2 * ROWS * NREC;       // [3][256]
    float* xb  = WoS + NOUT * NREC;          // [2][ROWS][12]

    const int tid = threadIdx.x;
    const int b0  = blockIdx.x * ROWS;
    const int c   = tid;                     // one output column per thread

    // ---- init SMEM ----
    for (int idx = tid; idx < NREC * JS; idx += NT){
        int cc = idx >> 7, j = idx & (JS - 1);
        Wsm[cc * WPAD + j] = W_rec[cc * NREC + j];
    }
    for (int idx = tid; idx < 2 * ROWS * NREC; idx += NT) rT[idx] = 0.f;
    for (int idx = tid; idx < NOUT * NREC; idx += NT) WoS[idx] = W_out[idx];
    if (tid < ROWS * NIN){
        int i = tid / NIN, k = tid % NIN;
        xb[i * 12 + k] = x[(size_t)(b0 + i) * TDIM * NIN + k];   // t=0 into buf 0
    }

    float win[NIN];
    #pragma unroll
    for (int k = 0; k < NIN; k++) win[k] = W_in[c * NIN + k];
    const float bs = bias[c];
    const float bo0 = b_out[0], bo1 = b_out[1], bo2 = b_out[2];

    float rs[ROWS];
    #pragma unroll
    for (int i = 0; i < ROWS; i++) rs[i] = 0.f;

    float nz[ROWS];
    #pragma unroll
    for (int i = 0; i < ROWS; i++)
        nz[i] = noise[(size_t)(b0 + i) * TDIM * NREC + c];
    double l2d = 0.0;
    __syncthreads();

    const int wid = tid >> 5, lane = tid & 31;   // warp w -> batch row w in epilogue

    const ulonglong2* __restrict__ wA = (const ulonglong2*)(Wsm + c * WPAD);
    const ulonglong2* __restrict__ gw = g_Wst;

    for (int t = 0; t < TDIM; t++){
        const int cur = t & 1, nxt = cur ^ 1;
        const float* rTc = rT + cur * ROWS * NREC;
        float*       rTn = rT + nxt * ROWS * NREC;
        const float* xbc = xb + cur * 96;
        float*       xbn = xb + nxt * 96;

        // u = bias + noise + x @ W_in^T
        float u[ROWS];
        #pragma unroll
        for (int i = 0; i < ROWS; i++) u[i] = bs + nz[i];
        #pragma unroll
        for (int i = 0; i < ROWS; i++){
            #pragma unroll
            for (int k = 0; k < NIN; k++)
                u[i] = fmaf(xbc[i * 12 + k], win[k], u[i]);
        }

        // prefetch next-step noise (hidden under GEMM)
        {
            int tn = (t + 1 < TDIM) ? t + 1 : t;
            #pragma unroll
            for (int i = 0; i < ROWS; i++)
                nz[i] = noise[((size_t)(b0 + i) * TDIM + tn) * NREC + c];
        }

        // accumulators: .x sums even-j, .y odd-j
        u64 acc[ROWS];
        #pragma unroll
        for (int i = 0; i < ROWS; i++) acc[i] = pk(u[i], 0.f);

        const ulonglong2* __restrict__ rr = (const ulonglong2*)rTc;  // [ROWS][64]

        // ---- phase A: j in [0,128), weights from SMEM ----
        #pragma unroll 8
        for (int jb = 0; jb < JS/4; jb++){
            ulonglong2 w = wA[jb];
            #pragma unroll
            for (int i = 0; i < ROWS; i++){
                ulonglong2 rv = rr[i * 64 + jb];
                acc[i] = fm2(rv.x, w.x, acc[i]);
                acc[i] = fm2(rv.y, w.y, acc[i]);
            }
        }
        // ---- phase B: j in [128,256), weights streamed from L2 (LDG.128) ----
        #pragma unroll 8
        for (int kb = 0; kb < NSTREAM; kb++){
            ulonglong2 w = gw[kb * NREC + c];
            #pragma unroll
            for (int i = 0; i < ROWS; i++){
                ulonglong2 rv = rr[i * 64 + JS/4 + kb];
                acc[i] = fm2(rv.x, w.x, acc[i]);
                acc[i] = fm2(rv.y, w.y, acc[i]);
            }
        }

        // r_new = 0.8 r + 0.2 relu(v);  v = .x + .y
        float ssum = 0.f;
        #pragma unroll
        for (int i = 0; i < ROWS; i++){
            float2 v = up(acc[i]);
            float vv = v.x + v.y;
            rs[i] = 0.8f * rs[i] + 0.2f * fmaxf(vv, 0.f);
            rTn[i * NREC + c] = rs[i];
            ssum = fmaf(rs[i], rs[i], ssum);
        }
        l2d += (double)ssum;

        // prefetch next x tile
        if (tid < ROWS * NIN){
            int i = tid / NIN, k = tid % NIN;
            int tn = (t + 1 < TDIM) ? t + 1 : t;
            xbn[i * 12 + k] = x[((size_t)(b0 + i) * TDIM + tn) * NIN + k];
        }

        __syncthreads();   // rTn complete

        // z = r_new @ W_out^T + b_out ; warp w -> batch row w
        {
            float z0 = 0.f, z1 = 0.f, z2 = 0.f;
            #pragma unroll
            for (int q = 0; q < NREC/32; q++){
                int jj = lane + 32 * q;
                float ra = rTn[wid * NREC + jj];
                z0 = fmaf(ra, WoS[jj],          z0);
                z1 = fmaf(ra, WoS[NREC + jj],   z1);
                z2 = fmaf(ra, WoS[2*NREC + jj], z2);
            }
            #pragma unroll
            for (int off = 16; off; off >>= 1){
                z0 += __shfl_down_sync(~0u, z0, off);
                z1 += __shfl_down_sync(~0u, z1, off);
                z2 += __shfl_down_sync(~0u, z2, off);
            }
            if (lane == 0){
                size_t ob = ((size_t)(b0 + wid) * TDIM + t) * NOUT;
                out[ob+0] = z0 + bo0; out[ob+1] = z1 + bo1; out[ob+2] = z2 + bo2;
            }
        }
    }

    // ---- deterministic l2 reduction, last-block finalization ----
    __syncthreads();
    double* dd = (double*)sm;
    dd[tid] = l2d;
    __syncthreads();
    if (tid == 0){
        double s = 0.0;
        #pragma unroll 8
        for (int i = 0; i < NT; i++) s += dd[i];
        g_l2p[blockIdx.x] = (float)s;
        __threadfence();
        unsigned int old = atomicInc(&g_ctr, NB - 1);
        if (old == NB - 1){
            __threadfence();
            double tot = 0.0;
            for (int i = 0; i < NB; i++) tot += (double)g_l2p[i];
            out[out_size - 1] = (float)(tot / ((double)TDIM * BATCH * NREC));
        }
    }
}

extern "C" void kernel_launch(void* const* d_in, const int* in_sizes, int n_in,
                              void* d_out, int out_size)
{
    const float* x     = (const float*)d_in[0];
    const float* noise = (const float*)d_in[1];
    const float* W_in  = (const float*)d_in[2];
    const float* W_rec = (const float*)d_in[3];
    const float* W_out = (const float*)d_in[4];
    const float* b_out = (const float*)d_in[5];
    const float* bias  = (const float*)d_in[6];
    float* out = (float*)d_out;

    size_t smem = (size_t)(NREC*WPAD + 2*ROWS*NREC + NOUT*NREC + 2*96) * sizeof(float);
    cudaFuncSetAttribute(rnn_kernel, cudaFuncAttributeMaxDynamicSharedMemorySize, (int)smem);

    prep_kernel<<<1, 256>>>(W_rec);
    rnn_kernel<<<NB, NT, smem>>>(x, noise, W_in, W_rec, W_out, b_out, bias, out, out_size);
}

// round 5
// speedup vs baseline: 1.0559x; 1.0559x over previous
#include <cuda_runtime.h>

#define TDIM 512
#define NREC 256
#define NIN 10
#define NOUT 3
#define BATCH 1024
#define ROWS 8
#define NB (BATCH/ROWS)     // 128 blocks
#define NT 256              // 8 warps, 2 per SMSP
#define HALF 128
#define JS 128              // j-half per thread group
#define WPAD 132            // padded W row (floats): conflict-free LDS.128
#define NSTREAM (JS/4)      // 32 packs of 4 j streamed from L2 (phase B)

typedef unsigned long long u64;

__device__ ulonglong2 g_Wst[NSTREAM * NREC];   // [kb][c] : W_rec[c][128+4kb..+3], 128 KB
__device__ float g_l2p[NB];
__device__ unsigned int g_ctr;

static __device__ __forceinline__ u64 pk(float a, float b){
    u64 r; asm("mov.b64 %0,{%1,%2};":"=l"(r):"f"(a),"f"(b)); return r;
}
static __device__ __forceinline__ u64 fm2(u64 a, u64 b, u64 c){
    u64 d; asm("fma.rn.f32x2 %0,%1,%2,%3;":"=l"(d):"l"(a),"l"(b),"l"(c)); return d;
}
static __device__ __forceinline__ u64 ad2(u64 a, u64 b){
    u64 d; asm("add.rn.f32x2 %0,%1,%2;":"=l"(d):"l"(a),"l"(b)); return d;
}
static __device__ __forceinline__ float2 up(u64 v){
    float2 f; asm("mov.b64 {%0,%1},%2;":"=f"(f.x),"=f"(f.y):"l"(v)); return f;
}

__global__ void prep_kernel(const float* __restrict__ W){
    int c = threadIdx.x;   // 256 threads
    const ulonglong2* row = (const ulonglong2*)(W + c * NREC);
    #pragma unroll
    for (int k = 0; k < NSTREAM; k++)
        g_Wst[k * NREC + c] = row[JS/4 + k];
}

__global__ __launch_bounds__(NT, 1)
void rnn_kernel(const float* __restrict__ x,
                const float* __restrict__ noise,
                const float* __restrict__ W_in,
                const float* __restrict__ W_rec,
                const float* __restrict__ W_out,
                const float* __restrict__ b_out,
                const float* __restrict__ bias,
                float* __restrict__ out, int out_size)
{
    extern __shared__ float sm[];
    float* Wsm = sm;                          // [256 c][WPAD] j<128, 135 KB
    float* rT  = Wsm + NREC * WPAD;           // [2][ROWS][NREC] double-buffered
    u64*   ps  = (u64*)(rT + 2 * ROWS * NREC);// [128 t][16] split-K partials, 16 KB
    float* WoS = (float*)(ps + HALF * 16);    // [3][256]
    float* xb  = WoS + NOUT * NREC;           // [2][ROWS][12]

    const int tid = threadIdx.x;
    const int b0  = blockIdx.x * ROWS;
    const bool lower = tid < HALF;
    const int t   = lower ? tid : tid - HALF;
    const int c0  = t;
    const int c1  = t + HALF;

    // ---- init SMEM ----
    for (int idx = tid; idx < NREC * JS; idx += NT){
        int cc = idx >> 7, j = idx & (JS - 1);
        Wsm[cc * WPAD + j] = W_rec[cc * NREC + j];
    }
    for (int idx = tid; idx < 2 * ROWS * NREC; idx += NT) rT[idx] = 0.f;
    for (int idx = tid; idx < NOUT * NREC; idx += NT) WoS[idx] = W_out[idx];
    if (tid < ROWS * NIN){
        int i = tid / NIN, k = tid % NIN;
        xb[i * 12 + k] = x[(size_t)(b0 + i) * TDIM * NIN + k];   // t=0 into buf 0
    }

    // lower half owns u (bias + noise + x W_in^T) and the state update
    float win0[NIN], win1[NIN];
    float bs0 = 0.f, bs1 = 0.f;
    if (lower){
        #pragma unroll
        for (int k = 0; k < NIN; k++){
            win0[k] = W_in[c0 * NIN + k];
            win1[k] = W_in[c1 * NIN + k];
        }
        bs0 = bias[c0]; bs1 = bias[c1];
    }
    const float bo0 = b_out[0], bo1 = b_out[1], bo2 = b_out[2];

    float r0[ROWS], r1[ROWS];
    #pragma unroll
    for (int i = 0; i < ROWS; i++){ r0[i] = 0.f; r1[i] = 0.f; }

    float nz0[ROWS], nz1[ROWS];
    if (lower){
        #pragma unroll
        for (int i = 0; i < ROWS; i++){
            size_t nb = (size_t)(b0 + i) * TDIM * NREC;
            nz0[i] = noise[nb + c0];
            nz1[i] = noise[nb + c1];
        }
    }
    double l2d = 0.0;
    __syncthreads();

    const int wid = tid >> 5, lane = tid & 31;

    const ulonglong2* __restrict__ wA0 = (const ulonglong2*)(Wsm + c0 * WPAD);
    const ulonglong2* __restrict__ wA1 = (const ulonglong2*)(Wsm + c1 * WPAD);
    const ulonglong2* __restrict__ gw  = g_Wst;

    for (int ts = 0; ts < TDIM; ts++){
        const int cur = ts & 1, nxt = cur ^ 1;
        const float* rTc = rT + cur * ROWS * NREC;
        float*       rTn = rT + nxt * ROWS * NREC;
        const float* xbc = xb + cur * 96;
        float*       xbn = xb + nxt * 96;
        const ulonglong2* __restrict__ rr = (const ulonglong2*)rTc;  // [ROWS][64]

        u64 a0[ROWS], a1[ROWS];

        if (lower){
            // u = bias + noise + x @ W_in^T
            float u0[ROWS], u1[ROWS];
            #pragma unroll
            for (int i = 0; i < ROWS; i++){ u0[i] = bs0 + nz0[i]; u1[i] = bs1 + nz1[i]; }
            #pragma unroll
            for (int i = 0; i < ROWS; i++){
                #pragma unroll
                for (int k = 0; k < NIN; k++){
                    float xv = xbc[i * 12 + k];
                    u0[i] = fmaf(xv, win0[k], u0[i]);
                    u1[i] = fmaf(xv, win1[k], u1[i]);
                }
            }
            // prefetch next-step noise (hidden under GEMM)
            int tn = (ts + 1 < TDIM) ? ts + 1 : ts;
            #pragma unroll
            for (int i = 0; i < ROWS; i++){
                size_t nb = ((size_t)(b0 + i) * TDIM + tn) * NREC;
                nz0[i] = noise[nb + c0];
                nz1[i] = noise[nb + c1];
            }
            #pragma unroll
            for (int i = 0; i < ROWS; i++){ a0[i] = pk(u0[i], 0.f); a1[i] = pk(u1[i], 0.f); }

            // phase A: j in [0,128), weights from SMEM
            #pragma unroll 8
            for (int jb = 0; jb < JS/4; jb++){
                ulonglong2 w0 = wA0[jb];
                ulonglong2 w1 = wA1[jb];
                #pragma unroll
                for (int i = 0; i < ROWS; i++){
                    ulonglong2 rv = rr[i * 64 + jb];
                    a0[i] = fm2(rv.x, w0.x, a0[i]);
                    a0[i] = fm2(rv.y, w0.y, a0[i]);
                    a1[i] = fm2(rv.x, w1.x, a1[i]);
                    a1[i] = fm2(rv.y, w1.y, a1[i]);
                }
            }
        } else {
            #pragma unroll
            for (int i = 0; i < ROWS; i++){ a0[i] = pk(0.f, 0.f); a1[i] = pk(0.f, 0.f); }

            // phase B: j in [128,256), weights streamed via LDG.128 (no crossbar)
            #pragma unroll 8
            for (int kb = 0; kb < NSTREAM; kb++){
                ulonglong2 w0 = gw[kb * NREC + c0];
                ulonglong2 w1 = gw[kb * NREC + c1];
                #pragma unroll
                for (int i = 0; i < ROWS; i++){
                    ulonglong2 rv = rr[i * 64 + JS/4 + kb];
                    a0[i] = fm2(rv.x, w0.x, a0[i]);
                    a0[i] = fm2(rv.y, w0.y, a0[i]);
                    a1[i] = fm2(rv.x, w1.x, a1[i]);
                    a1[i] = fm2(rv.y, w1.y, a1[i]);
                }
            }
            // publish partials
            ulonglong2* pw = (ulonglong2*)(ps + (size_t)t * 16);
            #pragma unroll
            for (int p = 0; p < 4; p++){
                pw[p]     = make_ulonglong2(a0[2*p], a0[2*p+1]);
                pw[4 + p] = make_ulonglong2(a1[2*p], a1[2*p+1]);
            }
            // upper half prefetches next x tile while lower finishes
            if (t < ROWS * NIN){
                int i = t / NIN, k = t % NIN;
                int tn = (ts + 1 < TDIM) ? ts + 1 : ts;
                xbn[i * 12 + k] = x[((size_t)(b0 + i) * TDIM + tn) * NIN + k];
            }
        }

        __syncthreads();   // partials visible

        if (lower){
            const u64* pr = ps + (size_t)t * 16;
            float ssum = 0.f;
            #pragma unroll
            for (int i = 0; i < ROWS; i++){
                float2 v0 = up(ad2(a0[i], pr[i]));
                float2 v1 = up(ad2(a1[i], pr[8 + i]));
                float vv0 = v0.x + v0.y;
                float vv1 = v1.x + v1.y;
                r0[i] = 0.8f * r0[i] + 0.2f * fmaxf(vv0, 0.f);
                r1[i] = 0.8f * r1[i] + 0.2f * fmaxf(vv1, 0.f);
                rTn[i * NREC + c0] = r0[i];
                rTn[i * NREC + c1] = r1[i];
                ssum = fmaf(r0[i], r0[i], ssum);
                ssum = fmaf(r1[i], r1[i], ssum);
            }
            l2d += (double)ssum;
        }

        __syncthreads();   // rTn complete

        // z = r_new @ W_out^T + b_out ; warp w -> batch row w (8 warps, 8 rows)
        {
            float z0 = 0.f, z1 = 0.f, z2 = 0.f;
            #pragma unroll
            for (int q = 0; q < NREC/32; q++){
                int jj = lane + 32 * q;
                float ra = rTn[wid * NREC + jj];
                z0 = fmaf(ra, WoS[jj],          z0);
                z1 = fmaf(ra, WoS[NREC + jj],   z1);
                z2 = fmaf(ra, WoS[2*NREC + jj], z2);
            }
            #pragma unroll
            for (int off = 16; off; off >>= 1){
                z0 += __shfl_down_sync(~0u, z0, off);
                z1 += __shfl_down_sync(~0u, z1, off);
                z2 += __shfl_down_sync(~0u, z2, off);
            }
            if (lane == 0){
                size_t ob = ((size_t)(b0 + wid) * TDIM + ts) * NOUT;
                out[ob+0] = z0 + bo0; out[ob+1] = z1 + bo1; out[ob+2] = z2 + bo2;
            }
        }
    }

    // ---- deterministic l2 reduction, last-block finalization ----
    __syncthreads();
    double* dd = (double*)sm;
    dd[tid] = l2d;
    __syncthreads();
    if (tid == 0){
        double s = 0.0;
        #pragma unroll 8
        for (int i = 0; i < NT; i++) s += dd[i];
        g_l2p[blockIdx.x] = (float)s;
        __threadfence();
        unsigned int old = atomicInc(&g_ctr, NB - 1);
        if (old == NB - 1){
            __threadfence();
            double tot = 0.0;
            for (int i = 0; i < NB; i++) tot += (double)g_l2p[i];
            out[out_size - 1] = (float)(tot / ((double)TDIM * BATCH * NREC));
        }
    }
}

extern "C" void kernel_launch(void* const* d_in, const int* in_sizes, int n_in,
                              void* d_out, int out_size)
{
    const float* x     = (const float*)d_in[0];
    const float* noise = (const float*)d_in[1];
    const float* W_in  = (const float*)d_in[2];
    const float* W_rec = (const float*)d_in[3];
    const float* W_out = (const float*)d_in[4];
    const float* b_out = (const float*)d_in[5];
    const float* bias  = (const float*)d_in[6];
    float* out = (float*)d_out;

    size_t smem = (size_t)(NREC*WPAD + 2*ROWS*NREC) * sizeof(float)
                + (size_t)HALF * 16 * sizeof(u64)
                + (size_t)(NOUT*NREC + 2*96) * sizeof(float);
    cudaFuncSetAttribute(rnn_kernel, cudaFuncAttributeMaxDynamicSharedMemorySize, (int)smem);

    prep_kernel<<<1, 256>>>(W_rec);
    rnn_kernel<<<NB, NT, smem>>>(x, noise, W_in, W_rec, W_out, b_out, bias, out, out_size);
}